// round 1
// baseline (speedup 1.0000x reference)
#include <cuda_runtime.h>
#include <cuda_bf16.h>
#include <cstdint>

// ---------------- problem constants ----------------
#define T 2048      // tokens (B*S)
#define H 1024      // hidden
#define E 8         // experts
#define TOPK 2
#define F 4096      // ffn dim
#define NSLOT (T*TOPK)   // 4096 dispatch slots
#define LN_EPS 1e-5f
#define GATE_EPS 1e-8f

// ---------------- scratch (device globals; no allocations allowed) ----------------
__device__ __nv_bfloat16 g_XN[(size_t)T * H];            // 4 MB  normalized tokens, bf16
__device__ __nv_bfloat16 g_GU[(size_t)NSLOT * (2*F)];    // 64 MB G (cols 0..F) and U (cols F..2F)
__device__ __nv_bfloat16 g_ACT[(size_t)NSLOT * F];       // 32 MB g*silu(u)
__device__ float         g_Y[(size_t)NSLOT * H];         // 16 MB expert outputs
__device__ int   g_cnt[E];
__device__ int   g_off[E];
__device__ int   g_tok_e[T*TOPK];
__device__ int   g_tok_p[T*TOPK];
__device__ float g_tok_w[T*TOPK];
__device__ int   g_tok_slot[T*TOPK];
__device__ int   g_slot_tok[NSLOT];

// ---------------- k0: zero counters ----------------
__global__ void k_zero() {
    if (threadIdx.x < E) g_cnt[threadIdx.x] = 0;
}

// ---------------- k1: layernorm + gating router ----------------
__global__ void __launch_bounds__(256) k_router(
    const float* __restrict__ x, const float* __restrict__ lnw,
    const float* __restrict__ lnb, const float* __restrict__ gw)
{
    int t = blockIdx.x, tid = threadIdx.x;
    int lane = tid & 31, wid = tid >> 5;
    const float* xr = x + (size_t)t * H;

    float v[4];
    float s = 0.f, s2 = 0.f;
#pragma unroll
    for (int i = 0; i < 4; i++) {
        float a = xr[tid + i * 256];
        v[i] = a; s += a; s2 += a * a;
    }
    __shared__ float sw[8], sw2[8], stat[2];
#pragma unroll
    for (int o = 16; o > 0; o >>= 1) {
        s  += __shfl_down_sync(0xffffffffu, s,  o);
        s2 += __shfl_down_sync(0xffffffffu, s2, o);
    }
    if (lane == 0) { sw[wid] = s; sw2[wid] = s2; }
    __syncthreads();
    if (wid == 0) {
        float a = (lane < 8) ? sw[lane]  : 0.f;
        float b = (lane < 8) ? sw2[lane] : 0.f;
#pragma unroll
        for (int o = 4; o > 0; o >>= 1) {
            a += __shfl_down_sync(0xffffffffu, a, o);
            b += __shfl_down_sync(0xffffffffu, b, o);
        }
        if (lane == 0) {
            float mean = a / (float)H;
            float var  = b / (float)H - mean * mean;
            stat[0] = mean;
            stat[1] = rsqrtf(var + LN_EPS);
        }
    }
    __syncthreads();
    float mean = stat[0], rstd = stat[1];

    float part[E];
#pragma unroll
    for (int e = 0; e < E; e++) part[e] = 0.f;
#pragma unroll
    for (int i = 0; i < 4; i++) {
        int h = tid + i * 256;
        float xn = (v[i] - mean) * rstd * lnw[h] + lnb[h];
        g_XN[(size_t)t * H + h] = __float2bfloat16(xn);
#pragma unroll
        for (int e = 0; e < E; e++) part[e] += xn * gw[e * H + h];
    }
    __shared__ float pl[8 * E];
#pragma unroll
    for (int e = 0; e < E; e++) {
        float p = part[e];
#pragma unroll
        for (int o = 16; o > 0; o >>= 1) p += __shfl_down_sync(0xffffffffu, p, o);
        if (lane == 0) pl[wid * E + e] = p;
    }
    __syncthreads();
    if (tid == 0) {
        float lg[E];
#pragma unroll
        for (int e = 0; e < E; e++) {
            float acc = 0.f;
            for (int w = 0; w < 8; w++) acc += pl[w * E + e];
            lg[e] = acc;
        }
        float m = lg[0];
#pragma unroll
        for (int e = 1; e < E; e++) m = fmaxf(m, lg[e]);
        float p[E], den = 0.f;
#pragma unroll
        for (int e = 0; e < E; e++) { p[e] = expf(lg[e] - m); den += p[e]; }
#pragma unroll
        for (int e = 0; e < E; e++) p[e] /= den;
        int e0 = 0;
#pragma unroll
        for (int e = 1; e < E; e++) if (p[e] > p[e0]) e0 = e;
        int e1 = -1;
#pragma unroll
        for (int e = 0; e < E; e++) {
            if (e == e0) continue;
            if (e1 < 0 || p[e] > p[e1]) e1 = e;
        }
        float g0 = p[e0], g1 = p[e1];
        float gs = g0 + g1 + GATE_EPS;
        g0 /= gs; g1 /= gs;
        int p0 = atomicAdd(&g_cnt[e0], 1);
        int p1 = atomicAdd(&g_cnt[e1], 1);
        g_tok_e[t*2]   = e0; g_tok_e[t*2+1] = e1;
        g_tok_p[t*2]   = p0; g_tok_p[t*2+1] = p1;
        g_tok_w[t*2]   = g0; g_tok_w[t*2+1] = g1;
    }
}

// ---------------- k2: offsets scan + aux loss ----------------
__global__ void k_scan(float* __restrict__ out, int out_size) {
    if (threadIdx.x == 0 && blockIdx.x == 0) {
        int off = 0;
        int c[E];
        for (int e = 0; e < E; e++) { c[e] = g_cnt[e]; g_off[e] = off; off += c[e]; }
        double tot = (double)off;
        double u[E], mean = 0.0;
        for (int e = 0; e < E; e++) { u[e] = (double)c[e] / tot; mean += u[e]; }
        mean /= (double)E;
        double var = 0.0;
        for (int e = 0; e < E; e++) { double d = u[e] - mean; var += d * d; }
        var /= (double)(E - 1);                 // ddof=1
        double lbl = var / (mean + 1e-8);
        lbl = lbl * lbl;
        if (out_size > T * H) out[T * H] = (float)lbl;
    }
}

// ---------------- k3: slot assignment ----------------
__global__ void k_assign() {
    int i = blockIdx.x * blockDim.x + threadIdx.x;
    if (i >= T * TOPK) return;
    int e = g_tok_e[i];
    int slot = g_off[e] + g_tok_p[i];
    g_tok_slot[i] = slot;
    g_slot_tok[slot] = i >> 1;
}

// ---------------- mma helper ----------------
__device__ __forceinline__ void mma16816(float* c, const uint32_t* a, const uint32_t* b) {
    asm volatile(
        "mma.sync.aligned.m16n8k16.row.col.f32.bf16.bf16.f32 "
        "{%0,%1,%2,%3}, {%4,%5,%6,%7}, {%8,%9}, {%0,%1,%2,%3};\n"
        : "+f"(c[0]), "+f"(c[1]), "+f"(c[2]), "+f"(c[3])
        : "r"(a[0]), "r"(a[1]), "r"(a[2]), "r"(a[3]), "r"(b[0]), "r"(b[1]));
}

#define BM 128
#define BN 128
#define BK 32
#define SPITCH 40   // bf16 elements per smem row (32 + 8 pad -> conflict-free frag loads)

// ---------------- k4: grouped GEMM  [n_e,H] x [8192,H]^T -> GU ----------------
__global__ void __launch_bounds__(256) k_gemmA(
    const float* __restrict__ Wg, const float* __restrict__ Wu)
{
    int e = blockIdx.z;
    int n_e = g_cnt[e];
    int rows0 = blockIdx.y * BM;
    if (rows0 >= n_e) return;
    int off = g_off[e];
    int mrows = min(BM, n_e - rows0);
    int col0 = blockIdx.x * BN;
    int tid = threadIdx.x;

    __shared__ __nv_bfloat16 As[BM * SPITCH];
    __shared__ __nv_bfloat16 Bs[BN * SPITCH];

    const __nv_bfloat16* aptr[2];
    int asmoff[2];
#pragma unroll
    for (int it = 0; it < 2; it++) {
        int idx = tid + it * 256;
        int row = idx >> 2, seg = idx & 3;
        asmoff[it] = row * SPITCH + seg * 8;
        if (row < mrows) {
            int tok = g_slot_tok[off + rows0 + row];
            aptr[it] = g_XN + (size_t)tok * H + seg * 8;
        } else aptr[it] = nullptr;
    }
    const float* bptr[4];
    int bsmoff[4];
#pragma unroll
    for (int it = 0; it < 4; it++) {
        int idx = tid + it * 256;
        int row = idx >> 3, seg = idx & 7;
        bsmoff[it] = row * SPITCH + seg * 4;
        int jj = col0 + row;
        const float* base = (jj < F) ? (Wg + ((size_t)e * F + jj) * (size_t)H)
                                     : (Wu + ((size_t)e * F + (jj - F)) * (size_t)H);
        bptr[it] = base + seg * 4;
    }

    int wid = tid >> 5, lane = tid & 31;
    int wm = wid & 3, wn = wid >> 2;
    int g = lane >> 2, tg = lane & 3;

    float acc[2][8][4];
#pragma unroll
    for (int mt = 0; mt < 2; mt++)
#pragma unroll
        for (int nt = 0; nt < 8; nt++)
#pragma unroll
            for (int q = 0; q < 4; q++) acc[mt][nt][q] = 0.f;

    for (int kk = 0; kk < H; kk += BK) {
#pragma unroll
        for (int it = 0; it < 2; it++) {
            uint4 val = make_uint4(0u, 0u, 0u, 0u);
            if (aptr[it]) val = *(const uint4*)(aptr[it] + kk);
            *(uint4*)&As[asmoff[it]] = val;
        }
#pragma unroll
        for (int it = 0; it < 4; it++) {
            float4 f = *(const float4*)(bptr[it] + kk);
            __nv_bfloat162 lo = __floats2bfloat162_rn(f.x, f.y);
            __nv_bfloat162 hi = __floats2bfloat162_rn(f.z, f.w);
            *(__nv_bfloat162*)&Bs[bsmoff[it]]     = lo;
            *(__nv_bfloat162*)&Bs[bsmoff[it] + 2] = hi;
        }
        __syncthreads();
#pragma unroll
        for (int ks = 0; ks < BK; ks += 16) {
            uint32_t afr[2][4], bfr[8][2];
#pragma unroll
            for (int mt = 0; mt < 2; mt++) {
                int rb = wm * 32 + mt * 16;
                afr[mt][0] = *(const uint32_t*)&As[(rb + g) * SPITCH + ks + tg * 2];
                afr[mt][1] = *(const uint32_t*)&As[(rb + g + 8) * SPITCH + ks + tg * 2];
                afr[mt][2] = *(const uint32_t*)&As[(rb + g) * SPITCH + ks + tg * 2 + 8];
                afr[mt][3] = *(const uint32_t*)&As[(rb + g + 8) * SPITCH + ks + tg * 2 + 8];
            }
#pragma unroll
            for (int nt = 0; nt < 8; nt++) {
                int cb = wn * 64 + nt * 8;
                bfr[nt][0] = *(const uint32_t*)&Bs[(cb + g) * SPITCH + ks + tg * 2];
                bfr[nt][1] = *(const uint32_t*)&Bs[(cb + g) * SPITCH + ks + tg * 2 + 8];
            }
#pragma unroll
            for (int mt = 0; mt < 2; mt++)
#pragma unroll
                for (int nt = 0; nt < 8; nt++)
                    mma16816(acc[mt][nt], afr[mt], bfr[nt]);
        }
        __syncthreads();
    }
#pragma unroll
    for (int mt = 0; mt < 2; mt++) {
        int r0l = wm * 32 + mt * 16 + g;
        int r1l = r0l + 8;
#pragma unroll
        for (int nt = 0; nt < 8; nt++) {
            int j = col0 + wn * 64 + nt * 8 + tg * 2;
            if (r0l < mrows) {
                __nv_bfloat162 o = __floats2bfloat162_rn(acc[mt][nt][0], acc[mt][nt][1]);
                *(__nv_bfloat162*)&g_GU[(size_t)(off + rows0 + r0l) * (2 * F) + j] = o;
            }
            if (r1l < mrows) {
                __nv_bfloat162 o = __floats2bfloat162_rn(acc[mt][nt][2], acc[mt][nt][3]);
                *(__nv_bfloat162*)&g_GU[(size_t)(off + rows0 + r1l) * (2 * F) + j] = o;
            }
        }
    }
}

// ---------------- k5: SwiGLU elementwise ----------------
__global__ void k_act() {
    size_t i8 = ((size_t)blockIdx.x * 256 + threadIdx.x) * 8;
    if (i8 >= (size_t)NSLOT * F) return;
    int slot = (int)(i8 >> 12);      // /F
    int f    = (int)(i8 & (F - 1));
    const __nv_bfloat16* gp = g_GU + (size_t)slot * (2 * F) + f;
    const __nv_bfloat16* up = gp + F;
    uint4 gv = *(const uint4*)gp;
    uint4 uv = *(const uint4*)up;
    __nv_bfloat162* gv2 = (__nv_bfloat162*)&gv;
    __nv_bfloat162* uv2 = (__nv_bfloat162*)&uv;
    uint4 ov;
    __nv_bfloat162* ov2 = (__nv_bfloat162*)&ov;
#pragma unroll
    for (int j = 0; j < 4; j++) {
        float2 gf = __bfloat1622float2(gv2[j]);
        float2 uf = __bfloat1622float2(uv2[j]);
        float a0 = gf.x * (uf.x / (1.f + expf(-uf.x)));
        float a1 = gf.y * (uf.y / (1.f + expf(-uf.y)));
        ov2[j] = __floats2bfloat162_rn(a0, a1);
    }
    *(uint4*)&g_ACT[(size_t)slot * F + f] = ov;
}

// ---------------- k6: grouped GEMM  [n_e,F] x [H,F]^T -> Y ----------------
__global__ void __launch_bounds__(256) k_gemmB(const float* __restrict__ Wd) {
    int e = blockIdx.z;
    int n_e = g_cnt[e];
    int rows0 = blockIdx.y * BM;
    if (rows0 >= n_e) return;
    int off = g_off[e];
    int mrows = min(BM, n_e - rows0);
    int col0 = blockIdx.x * BN;   // into H
    int tid = threadIdx.x;

    __shared__ __nv_bfloat16 As[BM * SPITCH];
    __shared__ __nv_bfloat16 Bs[BN * SPITCH];

    const __nv_bfloat16* aptr[2];
    int asmoff[2];
#pragma unroll
    for (int it = 0; it < 2; it++) {
        int idx = tid + it * 256;
        int row = idx >> 2, seg = idx & 3;
        asmoff[it] = row * SPITCH + seg * 8;
        if (row < mrows)
            aptr[it] = g_ACT + (size_t)(off + rows0 + row) * F + seg * 8;
        else aptr[it] = nullptr;
    }
    const float* bptr[4];
    int bsmoff[4];
#pragma unroll
    for (int it = 0; it < 4; it++) {
        int idx = tid + it * 256;
        int row = idx >> 3, seg = idx & 7;
        bsmoff[it] = row * SPITCH + seg * 4;
        int h = col0 + row;
        bptr[it] = Wd + ((size_t)e * H + h) * (size_t)F + seg * 4;
    }

    int wid = tid >> 5, lane = tid & 31;
    int wm = wid & 3, wn = wid >> 2;
    int g = lane >> 2, tg = lane & 3;

    float acc[2][8][4];
#pragma unroll
    for (int mt = 0; mt < 2; mt++)
#pragma unroll
        for (int nt = 0; nt < 8; nt++)
#pragma unroll
            for (int q = 0; q < 4; q++) acc[mt][nt][q] = 0.f;

    for (int kk = 0; kk < F; kk += BK) {
#pragma unroll
        for (int it = 0; it < 2; it++) {
            uint4 val = make_uint4(0u, 0u, 0u, 0u);
            if (aptr[it]) val = *(const uint4*)(aptr[it] + kk);
            *(uint4*)&As[asmoff[it]] = val;
        }
#pragma unroll
        for (int it = 0; it < 4; it++) {
            float4 f = *(const float4*)(bptr[it] + kk);
            __nv_bfloat162 lo = __floats2bfloat162_rn(f.x, f.y);
            __nv_bfloat162 hi = __floats2bfloat162_rn(f.z, f.w);
            *(__nv_bfloat162*)&Bs[bsmoff[it]]     = lo;
            *(__nv_bfloat162*)&Bs[bsmoff[it] + 2] = hi;
        }
        __syncthreads();
#pragma unroll
        for (int ks = 0; ks < BK; ks += 16) {
            uint32_t afr[2][4], bfr[8][2];
#pragma unroll
            for (int mt = 0; mt < 2; mt++) {
                int rb = wm * 32 + mt * 16;
                afr[mt][0] = *(const uint32_t*)&As[(rb + g) * SPITCH + ks + tg * 2];
                afr[mt][1] = *(const uint32_t*)&As[(rb + g + 8) * SPITCH + ks + tg * 2];
                afr[mt][2] = *(const uint32_t*)&As[(rb + g) * SPITCH + ks + tg * 2 + 8];
                afr[mt][3] = *(const uint32_t*)&As[(rb + g + 8) * SPITCH + ks + tg * 2 + 8];
            }
#pragma unroll
            for (int nt = 0; nt < 8; nt++) {
                int cb = wn * 64 + nt * 8;
                bfr[nt][0] = *(const uint32_t*)&Bs[(cb + g) * SPITCH + ks + tg * 2];
                bfr[nt][1] = *(const uint32_t*)&Bs[(cb + g) * SPITCH + ks + tg * 2 + 8];
            }
#pragma unroll
            for (int mt = 0; mt < 2; mt++)
#pragma unroll
                for (int nt = 0; nt < 8; nt++)
                    mma16816(acc[mt][nt], afr[mt], bfr[nt]);
        }
        __syncthreads();
    }
#pragma unroll
    for (int mt = 0; mt < 2; mt++) {
        int r0l = wm * 32 + mt * 16 + g;
        int r1l = r0l + 8;
#pragma unroll
        for (int nt = 0; nt < 8; nt++) {
            int j = col0 + wn * 64 + nt * 8 + tg * 2;
            if (r0l < mrows) {
                float2 o = make_float2(acc[mt][nt][0], acc[mt][nt][1]);
                *(float2*)&g_Y[(size_t)(off + rows0 + r0l) * H + j] = o;
            }
            if (r1l < mrows) {
                float2 o = make_float2(acc[mt][nt][2], acc[mt][nt][3]);
                *(float2*)&g_Y[(size_t)(off + rows0 + r1l) * H + j] = o;
            }
        }
    }
}

// ---------------- k7: combine + residual ----------------
__global__ void __launch_bounds__(256) k_combine(
    const float* __restrict__ x, float* __restrict__ out)
{
    int t = blockIdx.x, tid = threadIdx.x;
    int s0 = g_tok_slot[t * 2], s1 = g_tok_slot[t * 2 + 1];
    float w0 = g_tok_w[t * 2], w1 = g_tok_w[t * 2 + 1];
    const float4* xv = (const float4*)(x + (size_t)t * H);
    const float4* y0 = (const float4*)(g_Y + (size_t)s0 * H);
    const float4* y1 = (const float4*)(g_Y + (size_t)s1 * H);
    float4* ov = (float4*)(out + (size_t)t * H);
    float4 a = xv[tid], b = y0[tid], c = y1[tid];
    float4 r;
    r.x = a.x + w0 * b.x + w1 * c.x;
    r.y = a.y + w0 * b.y + w1 * c.y;
    r.z = a.z + w0 * b.z + w1 * c.z;
    r.w = a.w + w0 * b.w + w1 * c.w;
    ov[tid] = r;
}

// ---------------- launch ----------------
extern "C" void kernel_launch(void* const* d_in, const int* in_sizes, int n_in,
                              void* d_out, int out_size)
{
    const float* x    = (const float*)d_in[0];
    const float* lnw  = (const float*)d_in[1];
    const float* lnb  = (const float*)d_in[2];
    const float* gw   = (const float*)d_in[3];
    const float* Wg   = (const float*)d_in[4];
    const float* Wu   = (const float*)d_in[5];
    const float* Wd   = (const float*)d_in[6];
    float* out = (float*)d_out;

    k_zero<<<1, 32>>>();
    k_router<<<T, 256>>>(x, lnw, lnb, gw);
    k_scan<<<1, 32>>>(out, out_size);
    k_assign<<<(T * TOPK + 255) / 256, 256>>>();

    dim3 gA((2 * F) / BN, (T + BM - 1) / BM, E);   // (64,16,8)
    k_gemmA<<<gA, 256>>>(Wg, Wu);

    k_act<<<(int)(((size_t)NSLOT * F / 8 + 255) / 256), 256>>>();

    dim3 gB(H / BN, (T + BM - 1) / BM, E);         // (8,16,8)
    k_gemmB<<<gB, 256>>>(Wd);

    k_combine<<<T, 256>>>(x, out);
}